// round 13
// baseline (speedup 1.0000x reference)
#include <cuda_runtime.h>
#include <cuda_fp16.h>
#include <cstdint>

// ============================================================================
// Y[500000,256] = X @ W via mma.sync f16 m16n8k16 (f32 accum).
// R12: barrier-free mainloop. B persistent in smem (permuted frag order);
// A fragments loaded DIRECTLY from global (ld.global.nc.v2, full sectors),
// converted to f16 in regs, distance-2 pipelined over 16 k-steps. No
// producer warps, no __syncthreads after B-pack. Next-tile loads issued
// before the epilogue so stores cover their latency.
// 296 CTAs (2/SM), 8 warps, warp tile 32x64, v4 streaming epilogue.
// ============================================================================

#define D_DIM    256
#define N_HALF   128
#define M_TILE   128
#define NROWS_T  500000L
#define NTILES_T 3907        // ceil(500000/128)
#define NPAIRS   148
#define NCTA     296
#define NTHREADS 256

// smem: B frags [16 nt][16 ksg][32 lane][2 reg] f16x2 = 65536
#define SB_B       0
#define SMEM_TOTAL 65536     // << 114KB -> 2 CTAs/SM

// ---------------------------------------------------------------------------
__device__ __forceinline__ uint32_t smem_u32(const void* p) {
    uint32_t a;
    asm("{ .reg .u64 t; cvta.to.shared.u64 t, %1; cvt.u32.u64 %0, t; }"
        : "=r"(a) : "l"(p));
    return a;
}
__device__ __forceinline__ void sts128(uint32_t a, uint32_t x, uint32_t y,
                                       uint32_t z, uint32_t w) {
    asm volatile("st.shared.v4.b32 [%0], {%1,%2,%3,%4};"
                 :: "r"(a), "r"(x), "r"(y), "r"(z), "r"(w) : "memory");
}
__device__ __forceinline__ void sts16(uint32_t a, uint16_t v) {
    asm volatile("st.shared.u16 [%0], %1;" :: "r"(a), "h"(v) : "memory");
}
__device__ __forceinline__ uint2 lds64(uint32_t a) {
    uint2 v;
    asm volatile("ld.shared.v2.b32 {%0,%1}, [%2];" : "=r"(v.x), "=r"(v.y) : "r"(a));
    return v;
}
__device__ __forceinline__ float2 ldg2(const float* p) {
    float2 v;
    asm("ld.global.nc.v2.f32 {%0,%1}, [%2];" : "=f"(v.x), "=f"(v.y) : "l"(p));
    return v;
}
__device__ __forceinline__ void stg128_cs(float* p, float a, float b,
                                          float c, float d) {
    asm volatile("st.global.cs.v4.f32 [%0], {%1,%2,%3,%4};"
                 :: "l"(p), "f"(a), "f"(b), "f"(c), "f"(d) : "memory");
}
__device__ __forceinline__ uint32_t pack_h2(float a, float b) {
    __half2 h = __floats2half2_rn(a, b);     // a -> low, b -> high
    return *reinterpret_cast<uint32_t*>(&h);
}
// D(16x8,f32) += A(16x16,f16,row) * B(16x8,f16,col)
__device__ __forceinline__ void mma_f16(float* c, uint4 a, uint2 b) {
    asm volatile(
        "mma.sync.aligned.m16n8k16.row.col.f32.f16.f16.f32 "
        "{%0,%1,%2,%3}, {%4,%5,%6,%7}, {%8,%9}, {%0,%1,%2,%3};"
        : "+f"(c[0]), "+f"(c[1]), "+f"(c[2]), "+f"(c[3])
        : "r"(a.x), "r"(a.y), "r"(a.z), "r"(a.w), "r"(b.x), "r"(b.y));
}

// Load one k-step's A fragments (both mtiles) straight from X.
// pr[i] = X + rowclamped(i)*256 + tig*2 ; offsets in floats.
#define LDSTAGE(S, KS) do {                                                   \
    const int _o = (KS) * 16;                                                 \
    S[0] = ldg2(pr0 + _o);      S[1] = ldg2(pr1 + _o);                        \
    S[2] = ldg2(pr0 + _o + 8);  S[3] = ldg2(pr1 + _o + 8);                    \
    S[4] = ldg2(pr2 + _o);      S[5] = ldg2(pr3 + _o);                        \
    S[6] = ldg2(pr2 + _o + 8);  S[7] = ldg2(pr3 + _o + 8);                    \
} while (0)

// One k-step: cvt stage -> frags, refill stage (distance 2), lds B, 16 mmas.
#define KSTEP(S, KS) do {                                                     \
    uint4 A0, A1;                                                             \
    A0.x = pack_h2(S[0].x, S[0].y); A0.y = pack_h2(S[1].x, S[1].y);           \
    A0.z = pack_h2(S[2].x, S[2].y); A0.w = pack_h2(S[3].x, S[3].y);           \
    A1.x = pack_h2(S[4].x, S[4].y); A1.y = pack_h2(S[5].x, S[5].y);           \
    A1.z = pack_h2(S[6].x, S[6].y); A1.w = pack_h2(S[7].x, S[7].y);           \
    if ((KS) < 14) LDSTAGE(S, (KS) + 2);                                      \
    _Pragma("unroll")                                                         \
    for (int nt = 0; nt < 8; nt++) {                                          \
        uint2 bfr = lds64(bb + (uint32_t)((((ng * 8 + nt) * 16 + (KS)) * 32   \
                                           + lane) * 8));                     \
        mma_f16(acc[0][nt], A0, bfr);                                         \
        mma_f16(acc[1][nt], A1, bfr);                                         \
    }                                                                         \
} while (0)

// ---------------------------------------------------------------------------
// Fused build + persistent GEMM
// ---------------------------------------------------------------------------
__global__ void __launch_bounds__(NTHREADS, 2)
dag_gemm_kernel(const float* __restrict__ X,
                const float* __restrict__ wv,
                const int* __restrict__ rows,
                const int* __restrict__ cols,
                int nnz,
                float* __restrict__ Y) {
    extern __shared__ char smem[];
    const uint32_t sb = smem_u32(smem);
    const int tid  = threadIdx.x;
    const int w    = tid >> 5;
    const int lane = tid & 31;
    const int g    = lane >> 2;      // groupID
    const int tig  = lane & 3;       // thread-in-group
    const int cta  = blockIdx.x;
    const int h    = cta & 1;        // N-half
    const int pair = cta >> 1;
    const int ntiles = (NTILES_T - pair + NPAIRS - 1) / NPAIRS;

    // ---- build B-half f16 fragments in smem: zero, then scatter ----------
    // B_frag[nt(16)][ksg(16)][lane(32)][breg(2)] f16x2, with column
    // permutation so thread tig owns 16 contiguous Y cols (v4 epilogue):
    //   Y col c (within 64-col ng half) -> slot ((c&15)>>1)*8+((c>>4)<<1)+(c&1)
    #pragma unroll
    for (int i = 0; i < 16; i++)
        sts128(sb + SB_B + (uint32_t)(tid + (i << 8)) * 16, 0u, 0u, 0u, 0u);
    __syncthreads();
    for (int i = tid; i < nnz; i += NTHREADS) {
        int nl = cols[i] - h * N_HALF;
        if ((unsigned)nl < (unsigned)N_HALF) {
            int k    = rows[i];
            int ng_  = nl >> 6;
            int c    = nl & 63;
            int slot = (ng_ << 6) + ((c & 15) >> 1) * 8 + ((c >> 4) << 1) + (c & 1);
            int nt   = slot >> 3, gq = slot & 7;
            int ksg  = k >> 4,  wi = k & 15;
            int br   = wi >> 3, tg = (wi >> 1) & 3, lo = wi & 1;
            uint32_t a = sb + SB_B
                       + (uint32_t)(((nt * 16 + ksg) * 32 + gq * 4 + tg) * 8
                                    + br * 4 + lo * 2);
            __half hv = __float2half_rn(wv[i]);
            sts16(a, *reinterpret_cast<uint16_t*>(&hv));
        }
    }
    __syncthreads();   // B frags ready; NO MORE BARRIERS BELOW.

    const int mgid = w & 3;              // m-group
    const int ng   = w >> 2;             // n-group 0..1
    const uint32_t bb = sb + SB_B;

    float acc[2][8][4];
    #pragma unroll
    for (int mt = 0; mt < 2; mt++)
        #pragma unroll
        for (int nt = 0; nt < 8; nt++)
            #pragma unroll
            for (int q = 0; q < 4; q++) acc[mt][nt][q] = 0.0f;

    // row pointers for tile 0 (clamped: rows >= NROWS read row 0; those accs
    // are never stored)
    long m0 = (long)pair * M_TILE;
    const float *pr0, *pr1, *pr2, *pr3;
    {
        long mw = m0 + mgid * 32 + g;
        long r;
        r = mw;      if (r >= NROWS_T) r = 0;  pr0 = X + r * D_DIM + tig * 2;
        r = mw + 8;  if (r >= NROWS_T) r = 0;  pr1 = X + r * D_DIM + tig * 2;
        r = mw + 16; if (r >= NROWS_T) r = 0;  pr2 = X + r * D_DIM + tig * 2;
        r = mw + 24; if (r >= NROWS_T) r = 0;  pr3 = X + r * D_DIM + tig * 2;
    }
    float2 s0[8], s1[8];
    LDSTAGE(s0, 0);
    LDSTAGE(s1, 1);

    for (int j = 0; j < ntiles; j++) {
        // ---- 16 k-steps, distance-2 pipelined ---------------------------
        #pragma unroll
        for (int kk = 0; kk < 8; kk++) {
            KSTEP(s0, 2 * kk);
            KSTEP(s1, 2 * kk + 1);
        }

        const long mwst = m0 + mgid * 32;     // store base rows for THIS tile

        // ---- advance pointers + prefetch next tile's first 2 k-steps ----
        if (j + 1 < ntiles) {
            m0 += (long)NPAIRS * M_TILE;
            long mw = m0 + mgid * 32 + g;
            long r;
            r = mw;      if (r >= NROWS_T) r = 0;  pr0 = X + r * D_DIM + tig * 2;
            r = mw + 8;  if (r >= NROWS_T) r = 0;  pr1 = X + r * D_DIM + tig * 2;
            r = mw + 16; if (r >= NROWS_T) r = 0;  pr2 = X + r * D_DIM + tig * 2;
            r = mw + 24; if (r >= NROWS_T) r = 0;  pr3 = X + r * D_DIM + tig * 2;
            LDSTAGE(s0, 0);
            LDSTAGE(s1, 1);
        }

        // ---- epilogue: v4 streaming stores (covers prefetch latency) ----
        {
            const int cb = h * N_HALF + ng * 64 + tig * 16;
            #pragma unroll
            for (int mt = 0; mt < 2; mt++) {
                long r0 = mwst + mt * 16 + g;
                long r1 = r0 + 8;
                if (r0 < NROWS_T) {
                    float* d0 = Y + r0 * D_DIM + cb;
                    #pragma unroll
                    for (int jj = 0; jj < 4; jj++)
                        stg128_cs(d0 + jj * 4,
                                  acc[mt][2 * jj][0], acc[mt][2 * jj][1],
                                  acc[mt][2 * jj + 1][0], acc[mt][2 * jj + 1][1]);
                }
                if (r1 < NROWS_T) {
                    float* d1 = Y + r1 * D_DIM + cb;
                    #pragma unroll
                    for (int jj = 0; jj < 4; jj++)
                        stg128_cs(d1 + jj * 4,
                                  acc[mt][2 * jj][2], acc[mt][2 * jj][3],
                                  acc[mt][2 * jj + 1][2], acc[mt][2 * jj + 1][3]);
                }
                #pragma unroll
                for (int nt = 0; nt < 8; nt++)
                    #pragma unroll
                    for (int q = 0; q < 4; q++) acc[mt][nt][q] = 0.0f;
            }
        }
    }
}

// ---------------------------------------------------------------------------
extern "C" void kernel_launch(void* const* d_in, const int* in_sizes, int n_in,
                              void* d_out, int out_size) {
    const float* X    = (const float*)d_in[0];
    const float* wv   = (const float*)d_in[1];
    const int*   rows = (const int*)d_in[2];
    const int*   cols = (const int*)d_in[3];
    const int nnz = in_sizes[1];

    cudaFuncSetAttribute(dag_gemm_kernel,
                         cudaFuncAttributeMaxDynamicSharedMemorySize, SMEM_TOTAL);
    dag_gemm_kernel<<<NCTA, NTHREADS, SMEM_TOTAL>>>(X, wv, rows, cols, nnz,
                                                    (float*)d_out);
}

// round 15
// speedup vs baseline: 1.0355x; 1.0355x over previous
#include <cuda_runtime.h>
#include <cuda_fp16.h>
#include <cstdint>

// ============================================================================
// Y[500000,256] = X @ W via mma.sync f16 m16n8k16 (f32 accum).
// R13 = R10 (432us best) + paired-k B layout: one LDS.128 fetches B frags for
// TWO k-steps (halves B LDS instruction count; bytes unchanged).
//  - Coalesced LDG: each LDG.128 = 2 full rows x 256B contiguous.
//  - B-column permutation -> v4 streaming epilogue.
//  - 296 CTAs, 2/SM, regs capped 128.
// ============================================================================

#define D_DIM    256
#define N_HALF   128
#define M_TILE   128
#define K_CHUNK  64
#define NCHUNKS  4
#define NROWS_T  500000L
#define NTILES_T 3907        // ceil(500000/128)
#define NPAIRS   148
#define NCTA     296
#define NTHREADS 256

// smem layout (bytes):
//  B frags [16 nt][8 kp][32 lane][4 reg] f16x2 = 65536   (kp = ksg pair)
//  A frags 2 stages x [8 mt][4 ks][4 reg][32 lane] f16x2 = 32768
#define SB_B       0
#define SB_A       65536
#define A_STAGE_B  16384
#define SMEM_TOTAL (SB_A + 2 * A_STAGE_B)   // 98304 -> 2 CTAs/SM

// ---------------------------------------------------------------------------
__device__ __forceinline__ uint32_t smem_u32(const void* p) {
    uint32_t a;
    asm("{ .reg .u64 t; cvta.to.shared.u64 t, %1; cvt.u32.u64 %0, t; }"
        : "=r"(a) : "l"(p));
    return a;
}
__device__ __forceinline__ void sts128(uint32_t a, uint32_t x, uint32_t y,
                                       uint32_t z, uint32_t w) {
    asm volatile("st.shared.v4.b32 [%0], {%1,%2,%3,%4};"
                 :: "r"(a), "r"(x), "r"(y), "r"(z), "r"(w) : "memory");
}
__device__ __forceinline__ void sts64(uint32_t a, uint32_t x, uint32_t y) {
    asm volatile("st.shared.v2.b32 [%0], {%1,%2};"
                 :: "r"(a), "r"(x), "r"(y) : "memory");
}
__device__ __forceinline__ void sts16(uint32_t a, uint16_t v) {
    asm volatile("st.shared.u16 [%0], %1;" :: "r"(a), "h"(v) : "memory");
}
__device__ __forceinline__ uint32_t lds32(uint32_t a) {
    uint32_t v;
    asm volatile("ld.shared.b32 %0, [%1];" : "=r"(v) : "r"(a));
    return v;
}
__device__ __forceinline__ uint4 lds128(uint32_t a) {
    uint4 v;
    asm volatile("ld.shared.v4.b32 {%0,%1,%2,%3}, [%4];"
                 : "=r"(v.x), "=r"(v.y), "=r"(v.z), "=r"(v.w) : "r"(a));
    return v;
}
__device__ __forceinline__ void stg128_cs(float* p, float a, float b,
                                          float c, float d) {
    asm volatile("st.global.cs.v4.f32 [%0], {%1,%2,%3,%4};"
                 :: "l"(p), "f"(a), "f"(b), "f"(c), "f"(d) : "memory");
}
__device__ __forceinline__ uint32_t pack_h2(float a, float b) {
    __half2 h = __floats2half2_rn(a, b);     // a -> low, b -> high
    return *reinterpret_cast<uint32_t*>(&h);
}
// D(16x8,f32) += A(16x16,f16,row) * B(16x8,f16,col)
__device__ __forceinline__ void mma_f16(float* c, uint4 a, uint32_t b0,
                                        uint32_t b1) {
    asm volatile(
        "mma.sync.aligned.m16n8k16.row.col.f32.f16.f16.f32 "
        "{%0,%1,%2,%3}, {%4,%5,%6,%7}, {%8,%9}, {%0,%1,%2,%3};"
        : "+f"(c[0]), "+f"(c[1]), "+f"(c[2]), "+f"(c[3])
        : "r"(a.x), "r"(a.y), "r"(a.z), "r"(a.w), "r"(b0), "r"(b1));
}

// ---------------------------------------------------------------------------
// Fused build + persistent GEMM
// ---------------------------------------------------------------------------
__global__ void __launch_bounds__(NTHREADS, 2)
dag_gemm_kernel(const float* __restrict__ X,
                const float* __restrict__ wv,
                const int* __restrict__ rows,
                const int* __restrict__ cols,
                int nnz,
                float* __restrict__ Y) {
    extern __shared__ char smem[];
    const uint32_t sb = smem_u32(smem);
    const int tid  = threadIdx.x;
    const int w    = tid >> 5;
    const int lane = tid & 31;
    const int g    = lane >> 2;      // groupID
    const int tig  = lane & 3;       // thread-in-group
    const int cta  = blockIdx.x;
    const int h    = cta & 1;        // N-half
    const int pair = cta >> 1;
    const int ntiles = (NTILES_T - pair + NPAIRS - 1) / NPAIRS;

    // ---- build B-half f16 fragments in smem: zero, then scatter ----------
    // B_frag[nt(16)][kp(8)][lane(32)][4 reg] f16x2 (16B per lane entry):
    //   pair kp holds ksg = 2kp (bytes 0..7) and 2kp+1 (bytes 8..15).
    // Column PERMUTATION for v4 epilogue: within each 64-col ng-half,
    // Y col c maps to slot ((c&15)>>1)*8 + ((c>>4)<<1) + (c&1), so thread tig
    // owns 16 contiguous Y columns.
    #pragma unroll
    for (int i = 0; i < 16; i++)
        sts128(sb + SB_B + (uint32_t)(tid + (i << 8)) * 16, 0u, 0u, 0u, 0u);
    __syncthreads();
    for (int i = tid; i < nnz; i += NTHREADS) {
        int nl = cols[i] - h * N_HALF;
        if ((unsigned)nl < (unsigned)N_HALF) {
            int k    = rows[i];
            int ng_  = nl >> 6;
            int c    = nl & 63;
            int slot = (ng_ << 6) + ((c & 15) >> 1) * 8 + ((c >> 4) << 1) + (c & 1);
            int nt   = slot >> 3, gq = slot & 7;
            int ksg  = k >> 4,  wi = k & 15;
            int kp   = ksg >> 1, kh = ksg & 1;
            int br   = wi >> 3, tg = (wi >> 1) & 3, lo = wi & 1;
            uint32_t a = sb + SB_B
                       + (uint32_t)(((nt * 8 + kp) * 32 + gq * 4 + tg) * 16
                                    + kh * 8 + br * 4 + lo * 2);
            __half hv = __float2half_rn(wv[i]);
            sts16(a, *reinterpret_cast<uint16_t*>(&hv));
        }
    }

    // ---- producer mapping (coalesced): inst i loads row w*8+i+64*hi,
    //      float4 at k4 (lane = hi*16 + k4) => 2 rows x 256B per warp inst.
    const int k4  = lane & 15;
    const int hi  = lane >> 4;
    const int nchunks = ntiles * NCHUNKS;

    // warp tiling: 4 m-groups x 2 n-groups, warp tile 32x64
    const int mtg0 = (w & 3) * 2;           // first of 2 mtiles (of 8)
    const int ng   = (w >> 2);              // 0..1
    float acc[2][8][4];
    #pragma unroll
    for (int mt = 0; mt < 2; mt++)
        #pragma unroll
        for (int nt = 0; nt < 8; nt++)
            #pragma unroll
            for (int q = 0; q < 4; q++) acc[mt][nt][q] = 0.0f;

    // A-frag STS addresses, layout [mt(8)][ks(4)][reg(4)][lane-slot(32)] f16x2
    // with lane swizzle slot = (gq*4 + lo1*2) ^ (ks<<2) ^ (hi<<4).
    uint32_t a_sts[8];
    {
        const int ks  = k4 >> 2;
        const int lo1 = k4 & 1;
        const int l2h = (k4 >> 1) & 1;
        const int reg = (w & 1) + 2 * l2h;
        const int mt  = (w >> 1) + 4 * hi;
        #pragma unroll
        for (int i = 0; i < 8; i++) {
            int lnp = ((i * 4 + lo1 * 2) ^ (ks << 2)) ^ (hi << 4);
            a_sts[i] = (uint32_t)((((mt * 4 + ks) * 4 + reg) * 32 + lnp) * 4);
        }
    }

    __syncthreads();   // B frags ready

    uint2 u[8];
    // ---- prologue: load+convert chunk 0, store to stage 0 ----------------
    {
        long m0 = (long)pair * M_TILE;
        #pragma unroll
        for (int i = 0; i < 8; i++) {
            long grow = m0 + w * 8 + i + 64 * hi;
            float4 v = (grow < NROWS_T)
                ? *reinterpret_cast<const float4*>(X + grow * D_DIM + k4 * 4)
                : make_float4(0.f, 0.f, 0.f, 0.f);
            u[i].x = pack_h2(v.x, v.y);
            u[i].y = pack_h2(v.z, v.w);
        }
        uint32_t ab = sb + SB_A;
        #pragma unroll
        for (int i = 0; i < 8; i++)
            sts64(ab + a_sts[i], u[i].x, u[i].y);
    }

    for (int cg = 0; cg < nchunks; cg++) {
        __syncthreads();   // chunk cg resident in buffer cg&1

        const int j  = cg >> 2;       // tile
        const int ch = cg & 3;        // k-chunk (64)
        const long m0 = (long)(pair + (long)j * NPAIRS) * M_TILE;

        // prefetch + convert next chunk into registers (coalesced)
        if (cg + 1 < nchunks) {
            const int jn  = (cg + 1) >> 2;
            const int chn = (cg + 1) & 3;
            long m0n = (long)(pair + (long)jn * NPAIRS) * M_TILE;
            #pragma unroll
            for (int i = 0; i < 8; i++) {
                long grow = m0n + w * 8 + i + 64 * hi;
                float4 v = (grow < NROWS_T)
                    ? *reinterpret_cast<const float4*>(
                          X + grow * D_DIM + chn * K_CHUNK + k4 * 4)
                    : make_float4(0.f, 0.f, 0.f, 0.f);
                u[i].x = pack_h2(v.x, v.y);
                u[i].y = pack_h2(v.z, v.w);
            }
        }

        // ---- compute chunk: 2 k-pairs, B via LDS.128 (2 k-steps/fetch) ---
        {
            const uint32_t ab = sb + SB_A + (uint32_t)(cg & 1) * A_STAGE_B;
            const uint32_t bb = sb + SB_B;
            const uint32_t hswz = (uint32_t)(((mtg0 >> 2) & 1) << 4);
            #pragma unroll
            for (int kp = 0; kp < 2; kp++) {
                const int kse = kp * 2;        // local ks (even of pair)
                const int kso = kse + 1;       // local ks (odd of pair)
                const int kpg = ch * 2 + kp;   // global pair index 0..7
                // A frags for both sub-steps
                uint4 A0e, A1e, A0o, A1o;
                {
                    uint32_t lxe = (uint32_t)(((lane ^ (kse << 2)) ^ hswz) * 4);
                    uint32_t b0 = ab + (uint32_t)((mtg0 * 4 + kse) * 512) + lxe;
                    A0e.x = lds32(b0);       A0e.y = lds32(b0 + 128);
                    A0e.z = lds32(b0 + 256); A0e.w = lds32(b0 + 384);
                    uint32_t b1 = b0 + 2048;
                    A1e.x = lds32(b1);       A1e.y = lds32(b1 + 128);
                    A1e.z = lds32(b1 + 256); A1e.w = lds32(b1 + 384);
                    uint32_t lxo = (uint32_t)(((lane ^ (kso << 2)) ^ hswz) * 4);
                    uint32_t b2 = ab + (uint32_t)((mtg0 * 4 + kso) * 512) + lxo;
                    A0o.x = lds32(b2);       A0o.y = lds32(b2 + 128);
                    A0o.z = lds32(b2 + 256); A0o.w = lds32(b2 + 384);
                    uint32_t b3 = b2 + 2048;
                    A1o.x = lds32(b3);       A1o.y = lds32(b3 + 128);
                    A1o.z = lds32(b3 + 256); A1o.w = lds32(b3 + 384);
                }
                #pragma unroll
                for (int nt = 0; nt < 8; nt++) {
                    uint4 bq = lds128(bb + (uint32_t)((((ng * 8 + nt) * 8 + kpg) * 32
                                                      + lane) * 16));
                    mma_f16(acc[0][nt], A0e, bq.x, bq.y);
                    mma_f16(acc[1][nt], A1e, bq.x, bq.y);
                    mma_f16(acc[0][nt], A0o, bq.z, bq.w);
                    mma_f16(acc[1][nt], A1o, bq.z, bq.w);
                }
            }
        }

        // ---- epilogue on last chunk of tile (v4, contiguous 16 cols) -----
        if (ch == 3) {
            const long mw = m0 + (long)(w & 3) * 32;
            const int  cb = h * N_HALF + ng * 64 + tig * 16;  // 16 contiguous cols
            #pragma unroll
            for (int mt = 0; mt < 2; mt++) {
                long r0 = mw + mt * 16 + g;
                long r1 = r0 + 8;
                if (r0 < NROWS_T) {
                    float* d0 = Y + r0 * D_DIM + cb;
                    #pragma unroll
                    for (int jj = 0; jj < 4; jj++)
                        stg128_cs(d0 + jj * 4,
                                  acc[mt][2 * jj][0], acc[mt][2 * jj][1],
                                  acc[mt][2 * jj + 1][0], acc[mt][2 * jj + 1][1]);
                }
                if (r1 < NROWS_T) {
                    float* d1 = Y + r1 * D_DIM + cb;
                    #pragma unroll
                    for (int jj = 0; jj < 4; jj++)
                        stg128_cs(d1 + jj * 4,
                                  acc[mt][2 * jj][2], acc[mt][2 * jj][3],
                                  acc[mt][2 * jj + 1][2], acc[mt][2 * jj + 1][3]);
                }
                #pragma unroll
                for (int nt = 0; nt < 8; nt++)
                    #pragma unroll
                    for (int q = 0; q < 4; q++) acc[mt][nt][q] = 0.0f;
            }
        }

        // ---- store prefetched chunk into other buffer --------------------
        if (cg + 1 < nchunks) {
            uint32_t ab = sb + SB_A + (uint32_t)((cg + 1) & 1) * A_STAGE_B;
            #pragma unroll
            for (int i = 0; i < 8; i++)
                sts64(ab + a_sts[i], u[i].x, u[i].y);
        }
    }
}

// ---------------------------------------------------------------------------
extern "C" void kernel_launch(void* const* d_in, const int* in_sizes, int n_in,
                              void* d_out, int out_size) {
    const float* X    = (const float*)d_in[0];
    const float* wv   = (const float*)d_in[1];
    const int*   rows = (const int*)d_in[2];
    const int*   cols = (const int*)d_in[3];
    const int nnz = in_sizes[1];

    cudaFuncSetAttribute(dag_gemm_kernel,
                         cudaFuncAttributeMaxDynamicSharedMemorySize, SMEM_TOTAL);
    dag_gemm_kernel<<<NCTA, NTHREADS, SMEM_TOTAL>>>(X, wv, rows, cols, nnz,
                                                    (float*)d_out);
}

// round 16
// speedup vs baseline: 1.1141x; 1.0760x over previous
#include <cuda_runtime.h>
#include <cuda_fp16.h>
#include <cstdint>

// ============================================================================
// Y[500000,256] = X @ W via mma.sync f16 m16n8k16 (f32 accum).
// R15 = R10 (432us best) + two fixes:
//  1) A-frag STS bank-conflict fix: l2h XORed into slot bit0; producer uses
//     2x conflict-free sts32 per float4 (was 2-way-conflicted sts64);
//     consumer reads regs 2/3 at (base^4). Crossbar phases for STS halve.
//  2) STS(c+1) moved before the epilogue so the STG burst is off the
//     barrier-critical path.
// Everything else identical to R10: coalesced 2-row LDG.128, B-column
// permutation + v4 streaming epilogue, 296 CTAs (2/SM), regs capped 128.
// ============================================================================

#define D_DIM    256
#define N_HALF   128
#define M_TILE   128
#define K_CHUNK  64
#define NCHUNKS  4
#define NROWS_T  500000L
#define NTILES_T 3907        // ceil(500000/128)
#define NPAIRS   148
#define NCTA     296
#define NTHREADS 256

// smem layout (bytes):
//  B frags [16 nt][16 ksg][32 lane][2 reg] f16x2 = 65536
//  A frags 2 stages x [8 mt][4 ks][4 reg][32 slot] f16x2 = 32768
#define SB_B       0
#define SB_A       65536
#define A_STAGE_B  16384
#define SMEM_TOTAL (SB_A + 2 * A_STAGE_B)   // 98304 -> 2 CTAs/SM

// ---------------------------------------------------------------------------
__device__ __forceinline__ uint32_t smem_u32(const void* p) {
    uint32_t a;
    asm("{ .reg .u64 t; cvta.to.shared.u64 t, %1; cvt.u32.u64 %0, t; }"
        : "=r"(a) : "l"(p));
    return a;
}
__device__ __forceinline__ void sts128(uint32_t a, uint32_t x, uint32_t y,
                                       uint32_t z, uint32_t w) {
    asm volatile("st.shared.v4.b32 [%0], {%1,%2,%3,%4};"
                 :: "r"(a), "r"(x), "r"(y), "r"(z), "r"(w) : "memory");
}
__device__ __forceinline__ void sts32u(uint32_t a, uint32_t v) {
    asm volatile("st.shared.b32 [%0], %1;" :: "r"(a), "r"(v) : "memory");
}
__device__ __forceinline__ void sts16(uint32_t a, uint16_t v) {
    asm volatile("st.shared.u16 [%0], %1;" :: "r"(a), "h"(v) : "memory");
}
__device__ __forceinline__ uint32_t lds32(uint32_t a) {
    uint32_t v;
    asm volatile("ld.shared.b32 %0, [%1];" : "=r"(v) : "r"(a));
    return v;
}
__device__ __forceinline__ uint2 lds64(uint32_t a) {
    uint2 v;
    asm volatile("ld.shared.v2.b32 {%0,%1}, [%2];" : "=r"(v.x), "=r"(v.y) : "r"(a));
    return v;
}
__device__ __forceinline__ void stg128_cs(float* p, float a, float b,
                                          float c, float d) {
    asm volatile("st.global.cs.v4.f32 [%0], {%1,%2,%3,%4};"
                 :: "l"(p), "f"(a), "f"(b), "f"(c), "f"(d) : "memory");
}
__device__ __forceinline__ uint32_t pack_h2(float a, float b) {
    __half2 h = __floats2half2_rn(a, b);     // a -> low, b -> high
    return *reinterpret_cast<uint32_t*>(&h);
}
// D(16x8,f32) += A(16x16,f16,row) * B(16x8,f16,col)
__device__ __forceinline__ void mma_f16(float* c, uint4 a, uint2 b) {
    asm volatile(
        "mma.sync.aligned.m16n8k16.row.col.f32.f16.f16.f32 "
        "{%0,%1,%2,%3}, {%4,%5,%6,%7}, {%8,%9}, {%0,%1,%2,%3};"
        : "+f"(c[0]), "+f"(c[1]), "+f"(c[2]), "+f"(c[3])
        : "r"(a.x), "r"(a.y), "r"(a.z), "r"(a.w), "r"(b.x), "r"(b.y));
}

// ---------------------------------------------------------------------------
// Fused build + persistent GEMM
// ---------------------------------------------------------------------------
__global__ void __launch_bounds__(NTHREADS, 2)
dag_gemm_kernel(const float* __restrict__ X,
                const float* __restrict__ wv,
                const int* __restrict__ rows,
                const int* __restrict__ cols,
                int nnz,
                float* __restrict__ Y) {
    extern __shared__ char smem[];
    const uint32_t sb = smem_u32(smem);
    const int tid  = threadIdx.x;
    const int w    = tid >> 5;
    const int lane = tid & 31;
    const int g    = lane >> 2;      // groupID
    const int tig  = lane & 3;       // thread-in-group
    const int cta  = blockIdx.x;
    const int h    = cta & 1;        // N-half
    const int pair = cta >> 1;
    const int ntiles = (NTILES_T - pair + NPAIRS - 1) / NPAIRS;

    // ---- build B-half f16 fragments in smem: zero, then scatter ----------
    // B_frag[nt(16)][ksg(16)][lane(32)][breg(2)] f16x2, with column
    // permutation for the v4 epilogue: within each 64-col ng-half,
    // Y col c maps to slot ((c&15)>>1)*8 + ((c>>4)<<1) + (c&1), so thread
    // tig owns 16 contiguous Y columns.
    #pragma unroll
    for (int i = 0; i < 16; i++)
        sts128(sb + SB_B + (uint32_t)(tid + (i << 8)) * 16, 0u, 0u, 0u, 0u);
    __syncthreads();
    for (int i = tid; i < nnz; i += NTHREADS) {
        int nl = cols[i] - h * N_HALF;
        if ((unsigned)nl < (unsigned)N_HALF) {
            int k    = rows[i];
            int ng_  = nl >> 6;
            int c    = nl & 63;
            int slot = (ng_ << 6) + ((c & 15) >> 1) * 8 + ((c >> 4) << 1) + (c & 1);
            int nt   = slot >> 3, gq = slot & 7;
            int ksg  = k >> 4,  wi = k & 15;
            int br   = wi >> 3, tg = (wi >> 1) & 3, lo = wi & 1;
            uint32_t a = sb + SB_B
                       + (uint32_t)(((nt * 16 + ksg) * 32 + gq * 4 + tg) * 8
                                    + br * 4 + lo * 2);
            __half hv = __float2half_rn(wv[i]);
            sts16(a, *reinterpret_cast<uint16_t*>(&hv));
        }
    }

    // ---- producer mapping (coalesced): inst i loads row w*8+i+64*hi,
    //      float4 at k4 (lane = hi*16 + k4) => 2 rows x 256B per warp inst.
    const int k4  = lane & 15;
    const int hi  = lane >> 4;
    const int nchunks = ntiles * NCHUNKS;

    // warp tiling: 4 m-groups x 2 n-groups, warp tile 32x64
    const int mtg0 = (w & 3) * 2;           // first of 2 mtiles (of 8)
    const int ng   = (w >> 2);              // 0..1
    float acc[2][8][4];
    #pragma unroll
    for (int mt = 0; mt < 2; mt++)
        #pragma unroll
        for (int nt = 0; nt < 8; nt++)
            #pragma unroll
            for (int q = 0; q < 4; q++) acc[mt][nt][q] = 0.0f;

    // A-frag STS addresses, layout [mt(8)][ks(4)][reg(4)][slot(32)] f16x2.
    // slot = (i*4 + lo1*2 + j) ^ (ks<<2) ^ (hi<<4) ^ l2h  (j = word 0/1).
    // l2h in slot bit0 makes the producer store pattern cover all 32 banks
    // (conflict-free sts32 x2); consumer reads regs 2/3 at (base^4).
    uint32_t a_sts[8];
    {
        const int ks  = k4 >> 2;
        const int lo1 = k4 & 1;
        const int l2h = (k4 >> 1) & 1;
        const int reg = (w & 1) + 2 * l2h;
        const int mt  = (w >> 1) + 4 * hi;
        #pragma unroll
        for (int i = 0; i < 8; i++) {
            int lnp = ((i * 4 + lo1 * 2) ^ (ks << 2) ^ (hi << 4)) ^ l2h;
            a_sts[i] = (uint32_t)((((mt * 4 + ks) * 4 + reg) * 32 + lnp) * 4);
        }
    }

    __syncthreads();   // B frags ready

    uint2 u[8];
    // ---- prologue: load+convert chunk 0, store to stage 0 ----------------
    {
        long m0 = (long)pair * M_TILE;
        #pragma unroll
        for (int i = 0; i < 8; i++) {
            long grow = m0 + w * 8 + i + 64 * hi;
            float4 v = (grow < NROWS_T)
                ? *reinterpret_cast<const float4*>(X + grow * D_DIM + k4 * 4)
                : make_float4(0.f, 0.f, 0.f, 0.f);
            u[i].x = pack_h2(v.x, v.y);
            u[i].y = pack_h2(v.z, v.w);
        }
        uint32_t ab = sb + SB_A;
        #pragma unroll
        for (int i = 0; i < 8; i++) {
            uint32_t a0 = ab + a_sts[i];
            sts32u(a0, u[i].x);
            sts32u(a0 ^ 4, u[i].y);
        }
    }

    for (int cg = 0; cg < nchunks; cg++) {
        __syncthreads();   // chunk cg resident in buffer cg&1

        const int j  = cg >> 2;       // tile
        const int ch = cg & 3;        // k-chunk (64)
        const long m0 = (long)(pair + (long)j * NPAIRS) * M_TILE;

        // prefetch + convert next chunk into registers (coalesced)
        if (cg + 1 < nchunks) {
            const int jn  = (cg + 1) >> 2;
            const int chn = (cg + 1) & 3;
            long m0n = (long)(pair + (long)jn * NPAIRS) * M_TILE;
            #pragma unroll
            for (int i = 0; i < 8; i++) {
                long grow = m0n + w * 8 + i + 64 * hi;
                float4 v = (grow < NROWS_T)
                    ? *reinterpret_cast<const float4*>(
                          X + grow * D_DIM + chn * K_CHUNK + k4 * 4)
                    : make_float4(0.f, 0.f, 0.f, 0.f);
                u[i].x = pack_h2(v.x, v.y);
                u[i].y = pack_h2(v.z, v.w);
            }
        }

        // ---- compute chunk from smem buffer ------------------------------
        {
            const uint32_t ab = sb + SB_A + (uint32_t)(cg & 1) * A_STAGE_B;
            const uint32_t bb = sb + SB_B;
            const uint32_t hswz = (uint32_t)(((mtg0 >> 2) & 1) << 4);
            #pragma unroll
            for (int ks = 0; ks < 4; ks++) {
                const int ksg = ch * 4 + ks;
                const uint32_t lx = (uint32_t)(((lane ^ (ks << 2)) ^ hswz) * 4);
                uint4 a0, a1;
                {
                    uint32_t base0  = ab + (uint32_t)((mtg0 * 4 + ks) * 512) + lx;
                    uint32_t base0x = base0 ^ 4;          // slot^1 for regs 2,3
                    a0.x = lds32(base0);
                    a0.y = lds32(base0 + 128);
                    a0.z = lds32(base0x + 256);
                    a0.w = lds32(base0x + 384);
                    uint32_t base1  = base0 + 2048;       // next mt (same hi bit)
                    uint32_t base1x = base1 ^ 4;
                    a1.x = lds32(base1);
                    a1.y = lds32(base1 + 128);
                    a1.z = lds32(base1x + 256);
                    a1.w = lds32(base1x + 384);
                }
                uint2 bfr[8];
                #pragma unroll
                for (int nt = 0; nt < 8; nt++)
                    bfr[nt] = lds64(bb + (uint32_t)((((ng * 8 + nt) * 16 + ksg) * 32
                                                    + lane) * 8));
                #pragma unroll
                for (int nt = 0; nt < 8; nt++) {
                    mma_f16(acc[0][nt], a0, bfr[nt]);
                    mma_f16(acc[1][nt], a1, bfr[nt]);
                }
            }
        }

        // ---- store prefetched chunk FIRST (keeps barrier path short) -----
        if (cg + 1 < nchunks) {
            uint32_t ab = sb + SB_A + (uint32_t)((cg + 1) & 1) * A_STAGE_B;
            #pragma unroll
            for (int i = 0; i < 8; i++) {
                uint32_t a0 = ab + a_sts[i];
                sts32u(a0, u[i].x);
                sts32u(a0 ^ 4, u[i].y);
            }
        }

        // ---- epilogue on last chunk of tile (v4, contiguous 16 cols) -----
        if (ch == 3) {
            const long mw = m0 + (long)(w & 3) * 32;
            const int  cb = h * N_HALF + ng * 64 + tig * 16;  // 16 contiguous cols
            #pragma unroll
            for (int mt = 0; mt < 2; mt++) {
                long r0 = mw + mt * 16 + g;
                long r1 = r0 + 8;
                if (r0 < NROWS_T) {
                    float* d0 = Y + r0 * D_DIM + cb;
                    #pragma unroll
                    for (int jj = 0; jj < 4; jj++)
                        stg128_cs(d0 + jj * 4,
                                  acc[mt][2 * jj][0], acc[mt][2 * jj][1],
                                  acc[mt][2 * jj + 1][0], acc[mt][2 * jj + 1][1]);
                }
                if (r1 < NROWS_T) {
                    float* d1 = Y + r1 * D_DIM + cb;
                    #pragma unroll
                    for (int jj = 0; jj < 4; jj++)
                        stg128_cs(d1 + jj * 4,
                                  acc[mt][2 * jj][2], acc[mt][2 * jj][3],
                                  acc[mt][2 * jj + 1][2], acc[mt][2 * jj + 1][3]);
                }
                #pragma unroll
                for (int nt = 0; nt < 8; nt++)
                    #pragma unroll
                    for (int q = 0; q < 4; q++) acc[mt][nt][q] = 0.0f;
            }
        }
    }
}

// ---------------------------------------------------------------------------
extern "C" void kernel_launch(void* const* d_in, const int* in_sizes, int n_in,
                              void* d_out, int out_size) {
    const float* X    = (const float*)d_in[0];
    const float* wv   = (const float*)d_in[1];
    const int*   rows = (const int*)d_in[2];
    const int*   cols = (const int*)d_in[3];
    const int nnz = in_sizes[1];

    cudaFuncSetAttribute(dag_gemm_kernel,
                         cudaFuncAttributeMaxDynamicSharedMemorySize, SMEM_TOTAL);
    dag_gemm_kernel<<<NCTA, NTHREADS, SMEM_TOTAL>>>(X, wv, rows, cols, nnz,
                                                    (float*)d_out);
}